// round 10
// baseline (speedup 1.0000x reference)
#include <cuda_runtime.h>
#include <cuda_fp16.h>

#define N_NODES 100000
#define N_EDGES 1250000
#define D 64
#define NB 98          // scan blocks: ceil(N/1024)
#define PAD 18         // smem row stride (floats): 8B-aligned, conflict-light
#define NPB 6250       // nodeproj blocks (N/16)
#define EPB 200        // hist edges per nodeproj block (E/NPB)

// ---------------- scratch (static __device__ — allocation-free) ----------------
__device__ int   g_cnt[N_NODES];       // zero-init; k_scan re-zeroes after reading
__device__ int   g_scan_state[NB];     // lookback state; k_scatter re-zeroes for next replay
__device__ int   g_rowoff[N_NODES + 1];
__device__ int   g_cursor[N_NODES];
__device__ int   g_sorted_src[N_EDGES];
// per (node, lane): .x = half2(Q[2l],Q[2l+1]), .y = half2(R[2l],R[2l+1])
// Q = exp(-a_src-u), R = x_lin - u
__device__ uint2 g_pack2[N_NODES * 32];
__device__ float g_agg[N_NODES * D];   // aggregated messages (pre out-proj)

// ---------------- f32x2 packed helpers ----------------
__device__ __forceinline__ unsigned long long pack2(float lo, float hi) {
    unsigned long long r;
    asm("mov.b64 %0, {%1, %2};" : "=l"(r) : "f"(lo), "f"(hi));
    return r;
}
__device__ __forceinline__ void unpack2(unsigned long long v, float& lo, float& hi) {
    asm("mov.b64 {%0, %1}, %2;" : "=f"(lo), "=f"(hi) : "l"(v));
}
__device__ __forceinline__ unsigned long long fma2(unsigned long long a,
                                                   unsigned long long b,
                                                   unsigned long long c) {
    unsigned long long d;
    asm("fma.rn.f32x2 %0, %1, %2, %3;" : "=l"(d) : "l"(a), "l"(b), "l"(c));
    return d;
}
__device__ __forceinline__ unsigned long long add2(unsigned long long a,
                                                   unsigned long long b) {
    unsigned long long d;
    asm("add.rn.f32x2 %0, %1, %2;" : "=l"(d) : "l"(a), "l"(b));
    return d;
}
// half2 bits -> packed f32x2 (two F2F after ptxas folding)
__device__ __forceinline__ unsigned long long h2f2(unsigned int h) {
    unsigned long long r;
    asm("{ .reg .b16 a, b; .reg .f32 lo, hi;\n\t"
        "mov.b32 {a, b}, %1;\n\t"
        "cvt.f32.f16 lo, a;\n\t"
        "cvt.f32.f16 hi, b;\n\t"
        "mov.b64 %0, {lo, hi}; }"
        : "=l"(r) : "r"(h));
    return r;
}
// __half2 -> raw 32-bit (no such intrinsic in the half API; POD reinterpret)
__device__ __forceinline__ unsigned int h2bits(__half2 h) {
    return *reinterpret_cast<unsigned int*>(&h);
}

// int64-vs-int32 edge dtype probe (first 16 entries)
__device__ __forceinline__ int detect_is64(const void* eiv) {
    const long long* p = (const long long*)eiv;
    int is64 = 1;
#pragma unroll
    for (int j = 0; j < 16; j++) {
        long long v = p[j];
        if (v < 0 || v >= (long long)N_NODES) is64 = 0;
    }
    return is64;
}

__device__ __forceinline__ int load_idx(const void* eiv, int pos64, int is64) {
    if (is64) return (int)((const long long*)eiv)[pos64];
    return ((const int*)eiv)[pos64];
}

// ---------------- fused: node projections + hist slice ----------------
__global__ void k_nodehist(const void* __restrict__ eiv,
                           const float* __restrict__ x, const float* __restrict__ pos,
                           const float* __restrict__ W_in, const float* __restrict__ b_in,
                           const float* __restrict__ W_lin, const float* __restrict__ W_src,
                           const float* __restrict__ W_pos) {
    __shared__ float sh[D][PAD];
    __shared__ float spos[48];
    __shared__ int sflag;
    int c = threadIdx.x;
    int n0 = blockIdx.x * 16;

#pragma unroll
    for (int r = 0; r < 16; r++) sh[c][r] = x[(n0 + r) * D + c];
    if (c < 48) spos[c] = pos[n0 * 3 + c];
    if (c == 0) sflag = detect_is64(eiv);
    __syncthreads();

    // ---- hist slice (fire-and-forget atomics, overlap the GEMM phase) ----
    {
        int is64 = sflag;
        int base = blockIdx.x * EPB;
#pragma unroll
        for (int e = base + c; e < base + EPB; e += 64) {
            int d = load_idx(eiv, N_EDGES + e, is64);
            if ((unsigned)d < (unsigned)N_NODES) atomicAdd(&g_cnt[d], 1);
        }
    }

    // ---- GEMM 1: h = relu(x @ W_in + b_in) ----
    float bi = b_in[c];
    unsigned long long hp[8];
#pragma unroll
    for (int p = 0; p < 8; p++) hp[p] = pack2(bi, bi);
#pragma unroll 4
    for (int k = 0; k < D; k++) {
        float w = W_in[k * D + c];
        unsigned long long ww = pack2(w, w);
#pragma unroll
        for (int p = 0; p < 8; p++) {
            unsigned long long xp = *(const unsigned long long*)&sh[k][2 * p];
            hp[p] = fma2(xp, ww, hp[p]);
        }
    }
    float h[16];
#pragma unroll
    for (int p = 0; p < 8; p++) {
        unpack2(hp[p], h[2 * p], h[2 * p + 1]);
        h[2 * p]     = fmaxf(h[2 * p], 0.0f);
        h[2 * p + 1] = fmaxf(h[2 * p + 1], 0.0f);
    }
    __syncthreads();
#pragma unroll
    for (int r = 0; r < 16; r++) sh[c][r] = h[r];
    __syncthreads();

    // ---- GEMMs 2+3: x_lin = h@W_lin, a_src = h@W_src ----
    unsigned long long v1[8], v2[8];
#pragma unroll
    for (int p = 0; p < 8; p++) { v1[p] = 0ull; v2[p] = 0ull; }
#pragma unroll 4
    for (int k = 0; k < D; k++) {
        float w1 = W_lin[k * D + c];
        float w2 = W_src[k * D + c];
        unsigned long long ww1 = pack2(w1, w1);
        unsigned long long ww2 = pack2(w2, w2);
#pragma unroll
        for (int p = 0; p < 8; p++) {
            unsigned long long hpair = *(const unsigned long long*)&sh[k][2 * p];
            v1[p] = fma2(hpair, ww1, v1[p]);
            v2[p] = fma2(hpair, ww2, v2[p]);
        }
    }

    // ---- epilogue: Q/R -> half, pair-exchange, store (Qpair,Rpair) per lane ----
    float wp0 = W_pos[0 * D + c], wp1 = W_pos[1 * D + c], wp2 = W_pos[2 * D + c];
    int l = c >> 1;          // pack-entry lane this channel pair maps to
    int even = !(c & 1);
#pragma unroll
    for (int p = 0; p < 8; p++) {
        float xl0, xl1, as0, as1;
        unpack2(v1[p], xl0, xl1);
        unpack2(v2[p], as0, as1);
        int na = n0 + 2 * p, nb = na + 1;
        float u0 = fmaf(spos[(2 * p) * 3 + 2], wp2,
                   fmaf(spos[(2 * p) * 3 + 1], wp1, spos[(2 * p) * 3 + 0] * wp0));
        float u1 = fmaf(spos[(2 * p + 1) * 3 + 2], wp2,
                   fmaf(spos[(2 * p + 1) * 3 + 1], wp1, spos[(2 * p + 1) * 3 + 0] * wp0));
        // per node: v = half2(Q, R) for my channel
        unsigned int va = h2bits(__floats2half2_rn(__expf(-as0 - u0), xl0 - u0));
        unsigned int vb = h2bits(__floats2half2_rn(__expf(-as1 - u1), xl1 - u1));
        unsigned int oa = __shfl_xor_sync(0xffffffffu, va, 1);
        unsigned int ob = __shfl_xor_sync(0xffffffffu, vb, 1);
        if (even) {
            // (Q_even, Q_odd) and (R_even, R_odd)
            uint2 pa, pb;
            pa.x = __byte_perm(va, oa, 0x5410);
            pa.y = __byte_perm(va, oa, 0x7632);
            pb.x = __byte_perm(vb, ob, 0x5410);
            pb.y = __byte_perm(vb, ob, 0x7632);
            g_pack2[na * 32 + l] = pa;
            g_pack2[nb * 32 + l] = pb;
        }
    }
}

// ---------------- single-pass scan with decoupled lookback ----------------
__global__ void k_scan_lookback() {
    __shared__ int warpsum[32];
    __shared__ int s_prefix;
    int t = threadIdx.x;
    int b = blockIdx.x;
    int i = b * 1024 + t;
    int v = (i < N_NODES) ? g_cnt[i] : 0;
    if (i < N_NODES) g_cnt[i] = 0;

    int x = v;
#pragma unroll
    for (int o = 1; o < 32; o <<= 1) {
        int y = __shfl_up_sync(0xffffffffu, x, o);
        if ((t & 31) >= o) x += y;
    }
    if ((t & 31) == 31) warpsum[t >> 5] = x;
    __syncthreads();
    if (t < 32) {
        int w = warpsum[t];
#pragma unroll
        for (int o = 1; o < 32; o <<= 1) {
            int y = __shfl_up_sync(0xffffffffu, w, o);
            if (t >= o) w += y;
        }
        warpsum[t] = w;
    }
    __syncthreads();
    int wid = t >> 5;
    int incl = x + (wid ? warpsum[wid - 1] : 0);
    int block_agg = warpsum[31];

    if (t == 0) {
        if (b == 0) {
            atomicExch(&g_scan_state[0], (block_agg << 2) | 2);
            s_prefix = 0;
        } else {
            atomicExch(&g_scan_state[b], (block_agg << 2) | 1);
            int sum = 0;
            int j = b - 1;
            while (j >= 0) {
                int s = atomicAdd(&g_scan_state[j], 0);
                int st = s & 3;
                if (st == 0) continue;
                sum += (s >> 2);
                if (st == 2) break;
                j--;
            }
            s_prefix = sum;
            atomicExch(&g_scan_state[b], ((sum + block_agg) << 2) | 2);
        }
    }
    __syncthreads();
    int pre = s_prefix;

    int off = pre + incl - v;
    if (i < N_NODES) {
        g_rowoff[i] = off;
        g_cursor[i] = off;
    }
    if (i == N_NODES - 1) g_rowoff[N_NODES] = pre + incl;
}

// ---------------- scatter (also re-zeroes scan state for next replay) ----------------
__global__ void k_scatter(const void* __restrict__ eiv) {
    __shared__ int sflag;
    if (threadIdx.x == 0) sflag = detect_is64(eiv);
    __syncthreads();
    int is64 = sflag;

    int e = blockIdx.x * blockDim.x + threadIdx.x;
    if (blockIdx.x == 0 && threadIdx.x < NB) g_scan_state[threadIdx.x] = 0;
    if (e < N_EDGES) {
        int d = load_idx(eiv, N_EDGES + e, is64);
        int s = load_idx(eiv, e, is64);
        if ((unsigned)d < (unsigned)N_NODES) {
            int p = atomicAdd(&g_cursor[d], 1);
            g_sorted_src[p] = ((unsigned)s < (unsigned)N_NODES) ? s : 0;
        }
    }
}

// ---------------- edge pass: agg = (Σ Q·R)/(Σ Q) + (u[dst]+b_pos) ----------------
// warp per dst (8 dst / 256-thread block); lane owns channels {2l, 2l+1}.
// Per edge per lane: 1 shfl + 1 LDG.64 + 4 F2F + 1 add.f32x2 + 1 fma.f32x2.
__global__ void k_edge(const float* __restrict__ pos,
                       const float* __restrict__ W_pos, const float* __restrict__ b_pos) {
    int warp = threadIdx.x >> 5;
    int lane = threadIdx.x & 31;
    int dst = blockIdx.x * 8 + warp;
    if (dst >= N_NODES) return;

    int rs = g_rowoff[dst];
    int re = g_rowoff[dst + 1];

    unsigned long long sq = 0ull;   // (sum Q) for channels (2l, 2l+1)
    unsigned long long sr = 0ull;   // (sum Q*R)

    for (int base = rs; base < re; base += 32) {
        int m = min(32, re - base);
        int idx = (lane < m) ? g_sorted_src[base + lane] : 0;
        int j = 0;
        for (; j + 4 <= m; j += 4) {
            int s0 = __shfl_sync(0xffffffffu, idx, j);
            int s1 = __shfl_sync(0xffffffffu, idx, j + 1);
            int s2 = __shfl_sync(0xffffffffu, idx, j + 2);
            int s3 = __shfl_sync(0xffffffffu, idx, j + 3);
            uint2 v0 = g_pack2[s0 * 32 + lane];
            uint2 v1 = g_pack2[s1 * 32 + lane];
            uint2 v2 = g_pack2[s2 * 32 + lane];
            uint2 v3 = g_pack2[s3 * 32 + lane];
            unsigned long long q0 = h2f2(v0.x), r0 = h2f2(v0.y);
            unsigned long long q1 = h2f2(v1.x), r1 = h2f2(v1.y);
            unsigned long long q2 = h2f2(v2.x), r2 = h2f2(v2.y);
            unsigned long long q3 = h2f2(v3.x), r3 = h2f2(v3.y);
            sq = add2(sq, q0); sr = fma2(q0, r0, sr);
            sq = add2(sq, q1); sr = fma2(q1, r1, sr);
            sq = add2(sq, q2); sr = fma2(q2, r2, sr);
            sq = add2(sq, q3); sr = fma2(q3, r3, sr);
        }
        for (; j < m; j++) {
            int s0 = __shfl_sync(0xffffffffu, idx, j);
            uint2 v0 = g_pack2[s0 * 32 + lane];
            unsigned long long q0 = h2f2(v0.x), r0 = h2f2(v0.y);
            sq = add2(sq, q0); sr = fma2(q0, r0, sr);
        }
    }

    int c0 = 2 * lane;
    if (re > rs) {
        float sq0, sq1, sr0, sr1;
        unpack2(sq, sq0, sq1);
        unpack2(sr, sr0, sr1);
        float p0 = pos[dst * 3 + 0], p1 = pos[dst * 3 + 1], p2 = pos[dst * 3 + 2];
        float u0 = fmaf(p2, W_pos[2 * D + c0],     fmaf(p1, W_pos[1 * D + c0],     p0 * W_pos[0 * D + c0]));
        float u1 = fmaf(p2, W_pos[2 * D + c0 + 1], fmaf(p1, W_pos[1 * D + c0 + 1], p0 * W_pos[0 * D + c0 + 1]));
        g_agg[dst * D + c0]     = sr0 / sq0 + u0 + b_pos[c0];
        g_agg[dst * D + c0 + 1] = sr1 / sq1 + u1 + b_pos[c0 + 1];
    } else {
        g_agg[dst * D + c0]     = 0.0f;
        g_agg[dst * D + c0 + 1] = 0.0f;
    }
}

// ---------------- out projection: out = relu(agg @ W_out + b_out) ----------------
__global__ void k_outproj(const float* __restrict__ W_out, const float* __restrict__ b_out,
                          float* __restrict__ out) {
    __shared__ float sh[D][PAD];
    int c = threadIdx.x;
    int n0 = blockIdx.x * 16;

#pragma unroll
    for (int r = 0; r < 16; r++) sh[c][r] = g_agg[(n0 + r) * D + c];
    __syncthreads();

    float bo = b_out[c];
    unsigned long long op[8];
#pragma unroll
    for (int p = 0; p < 8; p++) op[p] = pack2(bo, bo);
#pragma unroll 4
    for (int k = 0; k < D; k++) {
        float w = W_out[k * D + c];
        unsigned long long ww = pack2(w, w);
#pragma unroll
        for (int p = 0; p < 8; p++) {
            unsigned long long ap = *(const unsigned long long*)&sh[k][2 * p];
            op[p] = fma2(ap, ww, op[p]);
        }
    }
#pragma unroll
    for (int p = 0; p < 8; p++) {
        float o0, o1;
        unpack2(op[p], o0, o1);
        out[(n0 + 2 * p) * D + c]     = fmaxf(o0, 0.0f);
        out[(n0 + 2 * p + 1) * D + c] = fmaxf(o1, 0.0f);
    }
}

// ---------------- launch ----------------
extern "C" void kernel_launch(void* const* d_in, const int* in_sizes, int n_in,
                              void* d_out, int out_size) {
    const float* x     = (const float*)d_in[0];
    const float* pos   = (const float*)d_in[1];
    const void*  ei    = d_in[2];
    const float* W_in  = (const float*)d_in[3];
    const float* b_in  = (const float*)d_in[4];
    const float* W_lin = (const float*)d_in[5];
    const float* W_src = (const float*)d_in[6];
    // d_in[7] = W_dst: dead (dst-side softmax terms cancel)
    const float* W_pos = (const float*)d_in[8];
    const float* b_pos = (const float*)d_in[9];
    const float* W_out = (const float*)d_in[10];
    const float* b_out = (const float*)d_in[11];
    float* out = (float*)d_out;

    k_nodehist<<<NPB, 64>>>(ei, x, pos, W_in, b_in, W_lin, W_src, W_pos);
    k_scan_lookback<<<NB, 1024>>>();
    k_scatter<<<(N_EDGES + 255) / 256, 256>>>(ei);
    k_edge<<<(N_NODES + 7) / 8, 256>>>(pos, W_pos, b_pos);
    k_outproj<<<N_NODES / 16, 64>>>(W_out, b_out, out);
}